// round 16
// baseline (speedup 1.0000x reference)
#include <cuda_runtime.h>
#include <cuda_bf16.h>
#include <cstdint>
#include <math.h>

// Problem dims
#define B 128
#define S 2048
#define H 512
#define V 32000
#define G 1536            // 3*H
#define NWARP_ATTN 16
#define CH_G 8            // k-split chunks for gates GEMM (K=512 -> 1 tile/chunk)
#define CH_C 16           // k-split chunks for concat GEMM (K=1024 -> 1 tile/chunk)

// ---------------- scratch (no allocs allowed) ----------------
__device__ float g_gpart[2 * CH_G * B * G];   // gates partials [set][chunk][b][j]
__device__ float g_cpart[CH_C * B * H];       // concat partials [chunk][b][j]
__device__ float g_hcat[B * 1024];            // [h_new | context] per row
__device__ __nv_bfloat16 g_ch[B * H];         // concat_out hi (bf16)
__device__ __nv_bfloat16 g_cl[B * H];         // concat_out lo (bf16)

// =================== HMMA GEMM: C = A @ W^T (+bias) ===================
// 3-term bf16 split: A*W ~= Ah*Wh + Ah*Wl + Al*Wh.
// CTA tile 128(M) x 128(N), K-tile 64. 512 threads / 16 warps: 4(M) x 4(N),
// warp tile 32x32. W through smem (ldmatrix); in the ABF16 path A fragments
// come straight from global (L1-resident) -- halves smem crossbar traffic.
// mode: 0 = bias + fp32 store, 1 = split-K partial store.

#define KT 64
#define NTHR 512
#define ASTRIDE 72                         // bf16/row in smem (64+8 pad); row 144B
#define TILE_ELEMS (128 * ASTRIDE)         // 9216 bf16
#define STAGE_BYTES (4 * TILE_ELEMS * 2)   // Ah, Al, Wh, Wl = 73728 B
#define GEMM_SMEM (2 * STAGE_BYTES)        // 147456 B

__device__ __forceinline__ uint32_t smem_u32(const void* p) {
    uint32_t a;
    asm("{ .reg .u64 t; cvta.to.shared.u64 t, %1; cvt.u32.u64 %0, t; }" : "=r"(a) : "l"(p));
    return a;
}
#define LDM4(r, addr)                                                                 \
    asm volatile("ldmatrix.sync.aligned.m8n8.x4.shared.b16 {%0,%1,%2,%3}, [%4];"      \
        : "=r"((r)[0]), "=r"((r)[1]), "=r"((r)[2]), "=r"((r)[3]) : "r"(addr))

__device__ __forceinline__ void mma16816(float* c, const uint32_t* a, const uint32_t* b) {
    asm volatile(
        "mma.sync.aligned.m16n8k16.row.col.f32.bf16.bf16.f32 "
        "{%0,%1,%2,%3}, {%4,%5,%6,%7}, {%8,%9}, {%0,%1,%2,%3};"
        : "+f"(c[0]), "+f"(c[1]), "+f"(c[2]), "+f"(c[3])
        : "r"(a[0]), "r"(a[1]), "r"(a[2]), "r"(a[3]), "r"(b[0]), "r"(b[1]));
}

__device__ __forceinline__ void cvt_store4(__nv_bfloat16* hi, __nv_bfloat16* lo,
                                           int base, float4 v) {
    float f[4] = {v.x, v.y, v.z, v.w};
#pragma unroll
    for (int p = 0; p < 2; p++) {
        float a0 = f[2 * p], a1 = f[2 * p + 1];
        __nv_bfloat16 h0 = __float2bfloat16(a0);
        __nv_bfloat16 h1 = __float2bfloat16(a1);
        __nv_bfloat16 l0 = __float2bfloat16(a0 - __bfloat162float(h0));
        __nv_bfloat16 l1 = __float2bfloat16(a1 - __bfloat162float(h1));
        __nv_bfloat162 th; th.x = h0; th.y = h1;
        __nv_bfloat162 tl; tl.x = l0; tl.y = l1;
        *(__nv_bfloat162*)(hi + base + 2 * p) = th;
        *(__nv_bfloat162*)(lo + base + 2 * p) = tl;
    }
}

template <bool ABF16>
__global__ __launch_bounds__(NTHR, 1) void k_gemm(
    const float* Aa, const float* Ab, const int* gia, const int* gib,
    const __nv_bfloat16* Agh, const __nv_bfloat16* Agl,
    const float* Wa, const float* Wb, const float* ba_, const float* bb_,
    float* Ca, float* Cb, int K, int ldc,
    int tilesPerChunk, int mode) {
    extern __shared__ char smc[];

    int tid = threadIdx.x;
    int wid = tid >> 5;
    int lane = tid & 31;
    int wm = (wid >> 2) * 32;       // 4 M groups of 32 rows
    int wn = (wid & 3) * 32;        // 4 N groups of 32 cols

    int set = blockIdx.y;
    const float* A = set ? Ab : Aa;
    const int* gidx = set ? gib : gia;
    const float* W = set ? Wb : Wa;
    const float* bias = set ? bb_ : ba_;
    float* C = set ? Cb : Ca;
    if (mode == 1) C += (size_t)blockIdx.z * 128 * ldc;

    int n0 = blockIdx.x * 128;
    int ktBase = blockIdx.z * tilesPerChunk;

    uint32_t sb = smem_u32(smc);
    uint32_t aLane = (uint32_t)(((lane & 7) + ((lane >> 3) & 1) * 8 + wm) * ASTRIDE +
                               (lane >> 4) * 8) * 2;
    uint32_t wLane = (uint32_t)(((lane & 7) + ((lane >> 3) >> 1) * 8 + wn) * ASTRIDE +
                               ((lane >> 3) & 1) * 8) * 2;
    uint32_t aH0 = sb + aLane;
    uint32_t aL0 = aH0 + TILE_ELEMS * 2;
    uint32_t wH0 = sb + 2 * TILE_ELEMS * 2 + wLane;
    uint32_t wL0 = wH0 + TILE_ELEMS * 2;

    // W load coords: 4 float4 per thread per tile (2048 float4 / 512 thr)
    int wrow[4], wkq[4];
#pragma unroll
    for (int ii = 0; ii < 4; ii++) {
        int q = tid + ii * NTHR;
        wrow[ii] = q >> 4;
        wkq[ii] = (q & 15) << 2;
    }
    int larow[4];
    if (!ABF16) {
#pragma unroll
        for (int ii = 0; ii < 4; ii++)
            larow[ii] = gidx ? gidx[wrow[ii]] : wrow[ii];
    }

    float acc[2][4][4];
#pragma unroll
    for (int i = 0; i < 2; i++)
#pragma unroll
        for (int j = 0; j < 4; j++)
#pragma unroll
            for (int c = 0; c < 4; c++) acc[i][j][c] = 0.f;

    float4 pw[4], pa[4];

    auto ldg_tile = [&](int kt) {
        int k0 = kt * KT;
#pragma unroll
        for (int ii = 0; ii < 4; ii++)
            pw[ii] = *(const float4*)(W + (size_t)(n0 + wrow[ii]) * K + k0 + wkq[ii]);
        if (!ABF16) {
#pragma unroll
            for (int ii = 0; ii < 4; ii++)
                pa[ii] = *(const float4*)(A + (size_t)larow[ii] * K + k0 + wkq[ii]);
        }
    };
    auto store_tile = [&](int stage) {
        char* base = smc + stage * STAGE_BYTES;
        __nv_bfloat16* Ahs = (__nv_bfloat16*)base;
        __nv_bfloat16* Als = Ahs + TILE_ELEMS;
        __nv_bfloat16* Whs = Ahs + 2 * TILE_ELEMS;
        __nv_bfloat16* Wls = Ahs + 3 * TILE_ELEMS;
#pragma unroll
        for (int ii = 0; ii < 4; ii++)
            cvt_store4(Whs, Wls, wrow[ii] * ASTRIDE + wkq[ii], pw[ii]);
        if (!ABF16) {
#pragma unroll
            for (int ii = 0; ii < 4; ii++)
                cvt_store4(Ahs, Als, wrow[ii] * ASTRIDE + wkq[ii], pa[ii]);
        }
    };
    // A-fragment global base for ABF16 path (row = wm + mt*16 + lane>>2)
    int ar0 = (lane >> 2);
    int akc = (lane & 3) * 2;

    auto do_ks = [&](int ks, uint32_t so, int kglob) {
        uint32_t kso = (uint32_t)ks * 32 + so;
        uint32_t ah[2][4], al[2][4], wf[2][4], wg[2][4];
        if (ABF16) {
            int kk = kglob + ks * 16 + akc;
#pragma unroll
            for (int mt = 0; mt < 2; mt++) {
                size_t gbase = (size_t)(wm + mt * 16 + ar0) * K + kk;
                ah[mt][0] = *(const uint32_t*)(Agh + gbase);
                ah[mt][1] = *(const uint32_t*)(Agh + gbase + 8 * (size_t)K);
                ah[mt][2] = *(const uint32_t*)(Agh + gbase + 8);
                ah[mt][3] = *(const uint32_t*)(Agh + gbase + 8 * (size_t)K + 8);
                al[mt][0] = *(const uint32_t*)(Agl + gbase);
                al[mt][1] = *(const uint32_t*)(Agl + gbase + 8 * (size_t)K);
                al[mt][2] = *(const uint32_t*)(Agl + gbase + 8);
                al[mt][3] = *(const uint32_t*)(Agl + gbase + 8 * (size_t)K + 8);
            }
        } else {
#pragma unroll
            for (int mt = 0; mt < 2; mt++) {
                LDM4(ah[mt], aH0 + mt * (16 * ASTRIDE * 2) + kso);
                LDM4(al[mt], aL0 + mt * (16 * ASTRIDE * 2) + kso);
            }
        }
#pragma unroll
        for (int p = 0; p < 2; p++) {
            LDM4(wf[p], wH0 + p * (16 * ASTRIDE * 2) + kso);
            LDM4(wg[p], wL0 + p * (16 * ASTRIDE * 2) + kso);
        }
#pragma unroll
        for (int mt = 0; mt < 2; mt++)
#pragma unroll
            for (int nt = 0; nt < 4; nt++) {
                const uint32_t* bh = &wf[nt >> 1][(nt & 1) * 2];
                const uint32_t* bl = &wg[nt >> 1][(nt & 1) * 2];
                mma16816(acc[mt][nt], ah[mt], bh);
                mma16816(acc[mt][nt], ah[mt], bl);
                mma16816(acc[mt][nt], al[mt], bh);
            }
    };

    // prologue: tile 0 -> stage 0
    ldg_tile(ktBase);
    store_tile(0);
    __syncthreads();

    for (int kt = 0; kt < tilesPerChunk; kt++) {
        int cur = kt & 1;
        uint32_t so = (uint32_t)cur * STAGE_BYTES;
        int kglob = (ktBase + kt) * KT;
        bool more = (kt + 1 < tilesPerChunk);

        if (more) ldg_tile(ktBase + kt + 1);   // overlaps MMAs below
#pragma unroll
        for (int ks = 0; ks < 4; ks++) do_ks(ks, so, kglob);
        if (more) store_tile(cur ^ 1);         // other stage: no reader this iter
        __syncthreads();
    }

    // ---- epilogue ----
#pragma unroll
    for (int mt = 0; mt < 2; mt++) {
        int r0 = wm + mt * 16 + (lane >> 2);
#pragma unroll
        for (int nt = 0; nt < 4; nt++) {
            int col = n0 + wn + nt * 8 + (lane & 3) * 2;
            float v0 = acc[mt][nt][0];
            float v1 = acc[mt][nt][1];
            float v2 = acc[mt][nt][2];
            float v3 = acc[mt][nt][3];
            if (mode == 0) {
                float b0 = bias[col], b1 = bias[col + 1];
                v0 += b0; v1 += b1; v2 += b0; v3 += b1;
            }
            *(float2*)(C + (size_t)r0 * ldc + col) = make_float2(v0, v1);
            *(float2*)(C + (size_t)(r0 + 8) * ldc + col) = make_float2(v2, v3);
        }
    }
}

// ---------------- concat split-K reduction + bias + tanh + bf16 split ----------------
__global__ void k_cfin(const float* __restrict__ bc) {
    int t = blockIdx.x * blockDim.x + threadIdx.x;   // t < B*H
    int b = t >> 9;
    int j = t & (H - 1);
    float sum = bc[j];
#pragma unroll
    for (int c = 0; c < CH_C; c++)
        sum += g_cpart[((size_t)c * B + b) * H + j];
    float v = tanhf(sum);
    __nv_bfloat16 h = __float2bfloat16(v);
    g_ch[t] = h;
    g_cl[t] = __float2bfloat16(v - __bfloat162float(h));
}

// ---------------- fused GRU + energies + online softmax + context + normalize ----------------
__device__ __forceinline__ void attn_row(const float4* __restrict__ er, float4* ev) {
#pragma unroll
    for (int i = 0; i < 4; i++) ev[i] = er[i * 32];
}

__global__ __launch_bounds__(512, 1) void k_attn(const float* __restrict__ enc,
                                                 float* __restrict__ attn_out,
                                                 const float* __restrict__ h0,
                                                 const float* __restrict__ bih,
                                                 const float* __restrict__ bhh,
                                                 float* __restrict__ out_h) {
    int b = blockIdx.x;
    int lane = threadIdx.x & 31;
    int warp = threadIdx.x >> 5;
    int t = threadIdx.x;

    __shared__ float sh_h[H];

    // ---- fused GRU: one h element per thread ----
    {
        int hh = t;
        float gir = bih[hh],  giz = bih[H + hh],  gin = bih[2 * H + hh];
        float ghr = bhh[hh],  ghz = bhh[H + hh],  ghn = bhh[2 * H + hh];
#pragma unroll
        for (int c = 0; c < CH_G; c++) {
            const float* p = g_gpart + ((size_t)c * B + b) * G;
            gir += p[hh]; giz += p[H + hh]; gin += p[2 * H + hh];
            const float* q = g_gpart + ((size_t)(CH_G + c) * B + b) * G;
            ghr += q[hh]; ghz += q[H + hh]; ghn += q[2 * H + hh];
        }
        float r = 1.f / (1.f + __expf(-(gir + ghr)));
        float z = 1.f / (1.f + __expf(-(giz + ghz)));
        float n = tanhf(gin + r * ghn);
        float hp = h0[b * H + hh];
        float hn = (1.f - z) * n + z * hp;
        sh_h[hh] = hn;
        g_hcat[b * 1024 + hh] = hn;
        out_h[b * H + hh] = hn;
    }
    __syncthreads();

    float4 hreg[4];
#pragma unroll
    for (int i = 0; i < 4; i++) hreg[i] = ((const float4*)sh_h)[lane + 32 * i];

    float m = -1e30f, l = 0.f;
    float4 ctx[4];
#pragma unroll
    for (int i = 0; i < 4; i++) ctx[i] = make_float4(0.f, 0.f, 0.f, 0.f);

    const float4* encb = (const float4*)(enc + (size_t)b * S * H) + lane;

    float4 ev0[4], ev1[4], ev2[4], ev3[4];
    attn_row(encb + (size_t)(warp) * (H / 4), ev0);
    attn_row(encb + (size_t)(warp + NWARP_ATTN) * (H / 4), ev1);
    attn_row(encb + (size_t)(warp + 2 * NWARP_ATTN) * (H / 4), ev2);
    attn_row(encb + (size_t)(warp + 3 * NWARP_ATTN) * (H / 4), ev3);

#define ATTN_STEP2(BUF0, BUF1, J)                                                  \
    do {                                                                           \
        int s0 = warp + (J) * NWARP_ATTN;                                          \
        int s1 = s0 + NWARP_ATTN;                                                  \
        float d0 = 0.f, d1 = 0.f;                                                  \
        _Pragma("unroll")                                                          \
        for (int i = 0; i < 4; i++) {                                              \
            d0 += hreg[i].x * BUF0[i].x + hreg[i].y * BUF0[i].y +                  \
                  hreg[i].z * BUF0[i].z + hreg[i].w * BUF0[i].w;                   \
            d1 += hreg[i].x * BUF1[i].x + hreg[i].y * BUF1[i].y +                  \
                  hreg[i].z * BUF1[i].z + hreg[i].w * BUF1[i].w;                   \
        }                                                                          \
        _Pragma("unroll")                                                          \
        for (int o = 16; o > 0; o >>= 1) {                                         \
            d0 += __shfl_xor_sync(0xffffffffu, d0, o);                             \
            d1 += __shfl_xor_sync(0xffffffffu, d1, o);                             \
        }                                                                          \
        if (lane == 0) {                                                           \
            attn_out[b * S + s0] = d0;                                             \
            attn_out[b * S + s1] = d1;                                             \
        }                                                                          \
        float mn = fmaxf(m, fmaxf(d0, d1));                                        \
        float scale = __expf(m - mn);                                              \
        float p0 = __expf(d0 - mn);                                                \
        float p1 = __expf(d1 - mn);                                                \
        l = l * scale + p0 + p1;                                                   \
        _Pragma("unroll")                                                          \
        for (int i = 0; i < 4; i++) {                                              \
            ctx[i].x = ctx[i].x * scale + p0 * BUF0[i].x + p1 * BUF1[i].x;         \
            ctx[i].y = ctx[i].y * scale + p0 * BUF0[i].y + p1 * BUF1[i].y;         \
            ctx[i].z = ctx[i].z * scale + p0 * BUF0[i].z + p1 * BUF1[i].z;         \
            ctx[i].w = ctx[i].w * scale + p0 * BUF0[i].w + p1 * BUF1[i].w;         \
        }                                                                          \
        m = mn;                                                                    \
        int sn0 = s0 + 4 * NWARP_ATTN;                                             \
        if (sn0 < S) {                                                             \
            attn_row(encb + (size_t)sn0 * (H / 4), BUF0);                          \
            attn_row(encb + (size_t)(sn0 + NWARP_ATTN) * (H / 4), BUF1);           \
        }                                                                          \
    } while (0)

#pragma unroll 1
    for (int j = 0; j < S / NWARP_ATTN; j += 4) {
        ATTN_STEP2(ev0, ev1, j);
        ATTN_STEP2(ev2, ev3, j + 2);
    }
#undef ATTN_STEP2

    __shared__ float sm_m[NWARP_ATTN];
    __shared__ float sm_l[NWARP_ATTN];
    __shared__ float sm_ctx[NWARP_ATTN][H];
#pragma unroll
    for (int i = 0; i < 4; i++)
        ((float4*)sm_ctx[warp])[lane + 32 * i] = ctx[i];
    if (lane == 0) { sm_m[warp] = m; sm_l[warp] = l; }
    __syncthreads();

    float mg = -1e30f;
#pragma unroll
    for (int w = 0; w < NWARP_ATTN; w++) mg = fmaxf(mg, sm_m[w]);
    float lg = 0.f, c = 0.f;
#pragma unroll
    for (int w = 0; w < NWARP_ATTN; w++) {
        float sc = __expf(sm_m[w] - mg);
        lg += sc * sm_l[w];
        c += sc * sm_ctx[w][t];
    }
    float inv = 1.f / lg;
    g_hcat[b * 1024 + 512 + t] = c * inv;

    for (int s = t; s < S; s += 512)
        attn_out[b * S + s] = __expf(attn_out[b * S + s] - mg) * inv;
}

// ---------------- launch ----------------
extern "C" void kernel_launch(void* const* d_in, const int* in_sizes, int n_in,
                              void* d_out, int out_size) {
    const int*   idx  = (const int*)  d_in[0];
    const float* h0   = (const float*)d_in[1];
    const float* enc  = (const float*)d_in[2];
    const float* emb  = (const float*)d_in[3];
    const float* wih  = (const float*)d_in[4];
    const float* whh  = (const float*)d_in[5];
    const float* bih  = (const float*)d_in[6];
    const float* bhh  = (const float*)d_in[7];
    const float* Wc   = (const float*)d_in[8];
    const float* bc   = (const float*)d_in[9];
    const float* Wout = (const float*)d_in[10];
    const float* bout = (const float*)d_in[11];

    float* out_logits = (float*)d_out;                 // B*V
    float* out_h      = out_logits + (size_t)B * V;    // B*H
    float* out_attn   = out_h + (size_t)B * H;         // B*S

    float* gp_p; cudaGetSymbolAddress((void**)&gp_p, g_gpart);
    float* cp_p; cudaGetSymbolAddress((void**)&cp_p, g_cpart);
    float* hc_p; cudaGetSymbolAddress((void**)&hc_p, g_hcat);
    __nv_bfloat16* ch_p; cudaGetSymbolAddress((void**)&ch_p, g_ch);
    __nv_bfloat16* cl_p; cudaGetSymbolAddress((void**)&cl_p, g_cl);

    cudaFuncSetAttribute(k_gemm<false>, cudaFuncAttributeMaxDynamicSharedMemorySize, GEMM_SMEM);
    cudaFuncSetAttribute(k_gemm<true>, cudaFuncAttributeMaxDynamicSharedMemorySize, GEMM_SMEM);

    // 1) GRU gate GEMMs (split-K x8): partials into g_gpart
    k_gemm<false><<<dim3(G / 128, 2, CH_G), NTHR, GEMM_SMEM>>>(
        emb, h0, idx, (const int*)nullptr,
        (const __nv_bfloat16*)nullptr, (const __nv_bfloat16*)nullptr,
        wih, whh, (const float*)nullptr, (const float*)nullptr,
        gp_p, gp_p + (size_t)CH_G * B * G,
        H, G, (H / KT) / CH_G, 1);
    // 2) fused GRU + attention
    k_attn<<<B, 512>>>(enc, out_attn, h0, bih, bhh, out_h);
    // 3) concat GEMM (split-K x16): partials into g_cpart
    k_gemm<false><<<dim3(H / 128, 1, CH_C), NTHR, GEMM_SMEM>>>(
        hc_p, hc_p, (const int*)nullptr, (const int*)nullptr,
        (const __nv_bfloat16*)nullptr, (const __nv_bfloat16*)nullptr,
        Wc, Wc, (const float*)nullptr, (const float*)nullptr,
        cp_p, cp_p,
        1024, H, (1024 / KT) / CH_C, 1);
    // 4) concat reduction + tanh + bf16 hi/lo split
    k_cfin<<<(B * H) / 256, 256>>>(bc);
    // 5) output GEMM (A pre-split bf16, fragments direct from global/L1)
    k_gemm<true><<<dim3(V / 128, 1, 1), NTHR, GEMM_SMEM>>>(
        (const float*)nullptr, (const float*)nullptr, (const int*)nullptr, (const int*)nullptr,
        ch_p, cl_p,
        Wout, Wout, bout, bout,
        out_logits, out_logits,
        H, V, H / KT, 0);
}

// round 17
// speedup vs baseline: 1.3363x; 1.3363x over previous
#include <cuda_runtime.h>
#include <cuda_bf16.h>
#include <cstdint>
#include <math.h>

// Problem dims
#define B 128
#define S 2048
#define H 512
#define V 32000
#define G 1536            // 3*H
#define NWARP_ATTN 16
#define CH_G 8            // k-split chunks for gates GEMM (K=512 -> 1 tile/chunk)
#define CH_C 16           // k-split chunks for concat GEMM (K=1024 -> 1 tile/chunk)

// ---------------- scratch (no allocs allowed) ----------------
__device__ float g_gpart[2 * CH_G * B * G];   // gates partials [set][chunk][b][j]
__device__ float g_cpart[CH_C * B * H];       // concat partials [chunk][b][j]
__device__ float g_hcat[B * 1024];            // [h_new | context] per row
__device__ __nv_bfloat16 g_ch[B * H];         // concat_out hi (bf16)
__device__ __nv_bfloat16 g_cl[B * H];         // concat_out lo (bf16)

// =================== HMMA GEMM: C = A @ W^T (+bias) ===================
// 3-term bf16 split: A*W ~= Ah*Wh + Ah*Wl + Al*Wh.
// CTA tile 128(M) x 128(N), K-tile 64. 512 threads / 16 warps: 4(M) x 4(N),
// warp tile 32x32. ldmatrix.x4 fragments; 2-stage smem, single barrier/tile.
// Smem fills use packed 8B STS.64 (one uint2 per plane per float4).
// mode: 0 = bias + fp32 store, 1 = split-K partial store.

#define KT 64
#define NTHR 512
#define ASTRIDE 72                         // bf16/row in smem (64+8 pad); row 144B
#define TILE_ELEMS (128 * ASTRIDE)         // 9216 bf16
#define STAGE_BYTES (4 * TILE_ELEMS * 2)   // Ah, Al, Wh, Wl = 73728 B
#define GEMM_SMEM (2 * STAGE_BYTES)        // 147456 B

__device__ __forceinline__ uint32_t smem_u32(const void* p) {
    uint32_t a;
    asm("{ .reg .u64 t; cvta.to.shared.u64 t, %1; cvt.u32.u64 %0, t; }" : "=r"(a) : "l"(p));
    return a;
}
#define LDM4(r, addr)                                                                 \
    asm volatile("ldmatrix.sync.aligned.m8n8.x4.shared.b16 {%0,%1,%2,%3}, [%4];"      \
        : "=r"((r)[0]), "=r"((r)[1]), "=r"((r)[2]), "=r"((r)[3]) : "r"(addr))

__device__ __forceinline__ void mma16816(float* c, const uint32_t* a, const uint32_t* b) {
    asm volatile(
        "mma.sync.aligned.m16n8k16.row.col.f32.bf16.bf16.f32 "
        "{%0,%1,%2,%3}, {%4,%5,%6,%7}, {%8,%9}, {%0,%1,%2,%3};"
        : "+f"(c[0]), "+f"(c[1]), "+f"(c[2]), "+f"(c[3])
        : "r"(a[0]), "r"(a[1]), "r"(a[2]), "r"(a[3]), "r"(b[0]), "r"(b[1]));
}

__device__ __forceinline__ uint32_t pack_bf16x2(float a0, float a1) {
    __nv_bfloat162 t;
    t.x = __float2bfloat16(a0);
    t.y = __float2bfloat16(a1);
    return *(uint32_t*)&t;
}

// split fp32x4 -> hi/lo bf16x4, single 8B store per plane
__device__ __forceinline__ void cvt_store4(__nv_bfloat16* hi, __nv_bfloat16* lo,
                                           int base, float4 v) {
    __nv_bfloat16 h0 = __float2bfloat16(v.x);
    __nv_bfloat16 h1 = __float2bfloat16(v.y);
    __nv_bfloat16 h2 = __float2bfloat16(v.z);
    __nv_bfloat16 h3 = __float2bfloat16(v.w);
    uint2 hv, lv;
    {
        __nv_bfloat162 a; a.x = h0; a.y = h1;
        __nv_bfloat162 b; b.x = h2; b.y = h3;
        hv.x = *(uint32_t*)&a; hv.y = *(uint32_t*)&b;
    }
    {
        __nv_bfloat162 a;
        a.x = __float2bfloat16(v.x - __bfloat162float(h0));
        a.y = __float2bfloat16(v.y - __bfloat162float(h1));
        __nv_bfloat162 b;
        b.x = __float2bfloat16(v.z - __bfloat162float(h2));
        b.y = __float2bfloat16(v.w - __bfloat162float(h3));
        lv.x = *(uint32_t*)&a; lv.y = *(uint32_t*)&b;
    }
    *(uint2*)(hi + base) = hv;
    *(uint2*)(lo + base) = lv;
}

template <bool ABF16>
__global__ __launch_bounds__(NTHR, 1) void k_gemm(
    const float* Aa, const float* Ab, const int* gia, const int* gib,
    const __nv_bfloat16* Agh, const __nv_bfloat16* Agl,
    const float* Wa, const float* Wb, const float* ba_, const float* bb_,
    float* Ca, float* Cb, int K, int ldc,
    int tilesPerChunk, int mode) {
    extern __shared__ char smc[];

    int tid = threadIdx.x;
    int wid = tid >> 5;
    int lane = tid & 31;
    int wm = (wid >> 2) * 32;       // 4 M groups of 32 rows
    int wn = (wid & 3) * 32;        // 4 N groups of 32 cols

    int set = blockIdx.y;
    const float* A = set ? Ab : Aa;
    const int* gidx = set ? gib : gia;
    const float* W = set ? Wb : Wa;
    const float* bias = set ? bb_ : ba_;
    float* C = set ? Cb : Ca;
    if (mode == 1) C += (size_t)blockIdx.z * 128 * ldc;

    int n0 = blockIdx.x * 128;
    int ktBase = blockIdx.z * tilesPerChunk;

    uint32_t sb = smem_u32(smc);
    uint32_t aLane = (uint32_t)(((lane & 7) + ((lane >> 3) & 1) * 8 + wm) * ASTRIDE +
                               (lane >> 4) * 8) * 2;
    uint32_t wLane = (uint32_t)(((lane & 7) + ((lane >> 3) >> 1) * 8 + wn) * ASTRIDE +
                               ((lane >> 3) & 1) * 8) * 2;
    uint32_t aH0 = sb + aLane;
    uint32_t aL0 = aH0 + TILE_ELEMS * 2;
    uint32_t wH0 = sb + 2 * TILE_ELEMS * 2 + wLane;
    uint32_t wL0 = wH0 + TILE_ELEMS * 2;

    // W load coords: 4 float4 per thread per tile (2048 float4 / 512 thr)
    int wrow[4], wkq[4];
#pragma unroll
    for (int ii = 0; ii < 4; ii++) {
        int q = tid + ii * NTHR;
        wrow[ii] = q >> 4;
        wkq[ii] = (q & 15) << 2;
    }
    // A (fp32): same coords. A (bf16): 2 uint4 (8 bf16) per plane (1024 / 512).
    int arow2[2], ac2[2], larow[4];
    if (ABF16) {
#pragma unroll
        for (int ii = 0; ii < 2; ii++) {
            int q = tid + ii * NTHR;
            arow2[ii] = q >> 3;
            ac2[ii] = (q & 7) << 3;
        }
    } else {
#pragma unroll
        for (int ii = 0; ii < 4; ii++)
            larow[ii] = gidx ? gidx[wrow[ii]] : wrow[ii];
    }

    float acc[2][4][4];
#pragma unroll
    for (int i = 0; i < 2; i++)
#pragma unroll
        for (int j = 0; j < 4; j++)
#pragma unroll
            for (int c = 0; c < 4; c++) acc[i][j][c] = 0.f;

    float4 pw[4], pa[4];
    uint4 ph[2], pl[2];

    auto ldg_tile = [&](int kt) {
        int k0 = kt * KT;
#pragma unroll
        for (int ii = 0; ii < 4; ii++)
            pw[ii] = *(const float4*)(W + (size_t)(n0 + wrow[ii]) * K + k0 + wkq[ii]);
        if (ABF16) {
#pragma unroll
            for (int ii = 0; ii < 2; ii++) {
                size_t g = (size_t)arow2[ii] * K + k0 + ac2[ii];
                ph[ii] = *(const uint4*)(Agh + g);
                pl[ii] = *(const uint4*)(Agl + g);
            }
        } else {
#pragma unroll
            for (int ii = 0; ii < 4; ii++)
                pa[ii] = *(const float4*)(A + (size_t)larow[ii] * K + k0 + wkq[ii]);
        }
    };
    auto store_tile = [&](int stage) {
        char* base = smc + stage * STAGE_BYTES;
        __nv_bfloat16* Ahs = (__nv_bfloat16*)base;
        __nv_bfloat16* Als = Ahs + TILE_ELEMS;
        __nv_bfloat16* Whs = Ahs + 2 * TILE_ELEMS;
        __nv_bfloat16* Wls = Ahs + 3 * TILE_ELEMS;
#pragma unroll
        for (int ii = 0; ii < 4; ii++)
            cvt_store4(Whs, Wls, wrow[ii] * ASTRIDE + wkq[ii], pw[ii]);
        if (ABF16) {
#pragma unroll
            for (int ii = 0; ii < 2; ii++) {
                int basei = arow2[ii] * ASTRIDE + ac2[ii];
                *(uint4*)(Ahs + basei) = ph[ii];
                *(uint4*)(Als + basei) = pl[ii];
            }
        } else {
#pragma unroll
            for (int ii = 0; ii < 4; ii++)
                cvt_store4(Ahs, Als, wrow[ii] * ASTRIDE + wkq[ii], pa[ii]);
        }
    };
    auto do_ks = [&](int ks, uint32_t so) {
        uint32_t kso = (uint32_t)ks * 32 + so;
        uint32_t ah[2][4], al[2][4], wf[2][4], wg[2][4];
#pragma unroll
        for (int mt = 0; mt < 2; mt++) {
            LDM4(ah[mt], aH0 + mt * (16 * ASTRIDE * 2) + kso);
            LDM4(al[mt], aL0 + mt * (16 * ASTRIDE * 2) + kso);
        }
#pragma unroll
        for (int p = 0; p < 2; p++) {
            LDM4(wf[p], wH0 + p * (16 * ASTRIDE * 2) + kso);
            LDM4(wg[p], wL0 + p * (16 * ASTRIDE * 2) + kso);
        }
#pragma unroll
        for (int mt = 0; mt < 2; mt++)
#pragma unroll
            for (int nt = 0; nt < 4; nt++) {
                const uint32_t* bh = &wf[nt >> 1][(nt & 1) * 2];
                const uint32_t* bl = &wg[nt >> 1][(nt & 1) * 2];
                mma16816(acc[mt][nt], ah[mt], bh);
                mma16816(acc[mt][nt], ah[mt], bl);
                mma16816(acc[mt][nt], al[mt], bh);
            }
    };

    // prologue: tile 0 -> stage 0
    ldg_tile(ktBase);
    store_tile(0);
    __syncthreads();

    for (int kt = 0; kt < tilesPerChunk; kt++) {
        int cur = kt & 1;
        uint32_t so = (uint32_t)cur * STAGE_BYTES;
        bool more = (kt + 1 < tilesPerChunk);

        if (more) ldg_tile(ktBase + kt + 1);   // overlaps MMAs below
#pragma unroll
        for (int ks = 0; ks < 4; ks++) do_ks(ks, so);
        if (more) store_tile(cur ^ 1);         // other stage: no reader this iter
        __syncthreads();
    }

    // ---- epilogue ----
#pragma unroll
    for (int mt = 0; mt < 2; mt++) {
        int r0 = wm + mt * 16 + (lane >> 2);
#pragma unroll
        for (int nt = 0; nt < 4; nt++) {
            int col = n0 + wn + nt * 8 + (lane & 3) * 2;
            float v0 = acc[mt][nt][0];
            float v1 = acc[mt][nt][1];
            float v2 = acc[mt][nt][2];
            float v3 = acc[mt][nt][3];
            if (mode == 0) {
                float b0 = bias[col], b1 = bias[col + 1];
                v0 += b0; v1 += b1; v2 += b0; v3 += b1;
            }
            *(float2*)(C + (size_t)r0 * ldc + col) = make_float2(v0, v1);
            *(float2*)(C + (size_t)(r0 + 8) * ldc + col) = make_float2(v2, v3);
        }
    }
}

// ---------------- concat split-K reduction + bias + tanh + bf16 split ----------------
__global__ void k_cfin(const float* __restrict__ bc) {
    int t = blockIdx.x * blockDim.x + threadIdx.x;   // t < B*H
    int b = t >> 9;
    int j = t & (H - 1);
    float sum = bc[j];
#pragma unroll
    for (int c = 0; c < CH_C; c++)
        sum += g_cpart[((size_t)c * B + b) * H + j];
    float v = tanhf(sum);
    __nv_bfloat16 h = __float2bfloat16(v);
    g_ch[t] = h;
    g_cl[t] = __float2bfloat16(v - __bfloat162float(h));
}

// ---------------- fused GRU + energies + online softmax + context + normalize ----------------
__device__ __forceinline__ void attn_row(const float4* __restrict__ er, float4* ev) {
#pragma unroll
    for (int i = 0; i < 4; i++) ev[i] = er[i * 32];
}

__global__ __launch_bounds__(512, 1) void k_attn(const float* __restrict__ enc,
                                                 float* __restrict__ attn_out,
                                                 const float* __restrict__ h0,
                                                 const float* __restrict__ bih,
                                                 const float* __restrict__ bhh,
                                                 float* __restrict__ out_h) {
    int b = blockIdx.x;
    int lane = threadIdx.x & 31;
    int warp = threadIdx.x >> 5;
    int t = threadIdx.x;

    __shared__ float sh_h[H];

    // ---- fused GRU: one h element per thread ----
    {
        int hh = t;
        float gir = bih[hh],  giz = bih[H + hh],  gin = bih[2 * H + hh];
        float ghr = bhh[hh],  ghz = bhh[H + hh],  ghn = bhh[2 * H + hh];
#pragma unroll
        for (int c = 0; c < CH_G; c++) {
            const float* p = g_gpart + ((size_t)c * B + b) * G;
            gir += p[hh]; giz += p[H + hh]; gin += p[2 * H + hh];
            const float* q = g_gpart + ((size_t)(CH_G + c) * B + b) * G;
            ghr += q[hh]; ghz += q[H + hh]; ghn += q[2 * H + hh];
        }
        float r = 1.f / (1.f + __expf(-(gir + ghr)));
        float z = 1.f / (1.f + __expf(-(giz + ghz)));
        float n = tanhf(gin + r * ghn);
        float hp = h0[b * H + hh];
        float hn = (1.f - z) * n + z * hp;
        sh_h[hh] = hn;
        g_hcat[b * 1024 + hh] = hn;
        out_h[b * H + hh] = hn;
    }
    __syncthreads();

    float4 hreg[4];
#pragma unroll
    for (int i = 0; i < 4; i++) hreg[i] = ((const float4*)sh_h)[lane + 32 * i];

    float m = -1e30f, l = 0.f;
    float4 ctx[4];
#pragma unroll
    for (int i = 0; i < 4; i++) ctx[i] = make_float4(0.f, 0.f, 0.f, 0.f);

    const float4* encb = (const float4*)(enc + (size_t)b * S * H) + lane;

    float4 ev0[4], ev1[4], ev2[4], ev3[4];
    attn_row(encb + (size_t)(warp) * (H / 4), ev0);
    attn_row(encb + (size_t)(warp + NWARP_ATTN) * (H / 4), ev1);
    attn_row(encb + (size_t)(warp + 2 * NWARP_ATTN) * (H / 4), ev2);
    attn_row(encb + (size_t)(warp + 3 * NWARP_ATTN) * (H / 4), ev3);

#define ATTN_STEP2(BUF0, BUF1, J)                                                  \
    do {                                                                           \
        int s0 = warp + (J) * NWARP_ATTN;                                          \
        int s1 = s0 + NWARP_ATTN;                                                  \
        float d0 = 0.f, d1 = 0.f;                                                  \
        _Pragma("unroll")                                                          \
        for (int i = 0; i < 4; i++) {                                              \
            d0 += hreg[i].x * BUF0[i].x + hreg[i].y * BUF0[i].y +                  \
                  hreg[i].z * BUF0[i].z + hreg[i].w * BUF0[i].w;                   \
            d1 += hreg[i].x * BUF1[i].x + hreg[i].y * BUF1[i].y +                  \
                  hreg[i].z * BUF1[i].z + hreg[i].w * BUF1[i].w;                   \
        }                                                                          \
        _Pragma("unroll")                                                          \
        for (int o = 16; o > 0; o >>= 1) {                                         \
            d0 += __shfl_xor_sync(0xffffffffu, d0, o);                             \
            d1 += __shfl_xor_sync(0xffffffffu, d1, o);                             \
        }                                                                          \
        if (lane == 0) {                                                           \
            attn_out[b * S + s0] = d0;                                             \
            attn_out[b * S + s1] = d1;                                             \
        }                                                                          \
        float mn = fmaxf(m, fmaxf(d0, d1));                                        \
        float scale = __expf(m - mn);                                              \
        float p0 = __expf(d0 - mn);                                                \
        float p1 = __expf(d1 - mn);                                                \
        l = l * scale + p0 + p1;                                                   \
        _Pragma("unroll")                                                          \
        for (int i = 0; i < 4; i++) {                                              \
            ctx[i].x = ctx[i].x * scale + p0 * BUF0[i].x + p1 * BUF1[i].x;         \
            ctx[i].y = ctx[i].y * scale + p0 * BUF0[i].y + p1 * BUF1[i].y;         \
            ctx[i].z = ctx[i].z * scale + p0 * BUF0[i].z + p1 * BUF1[i].z;         \
            ctx[i].w = ctx[i].w * scale + p0 * BUF0[i].w + p1 * BUF1[i].w;         \
        }                                                                          \
        m = mn;                                                                    \
        int sn0 = s0 + 4 * NWARP_ATTN;                                             \
        if (sn0 < S) {                                                             \
            attn_row(encb + (size_t)sn0 * (H / 4), BUF0);                          \
            attn_row(encb + (size_t)(sn0 + NWARP_ATTN) * (H / 4), BUF1);           \
        }                                                                          \
    } while (0)

#pragma unroll 1
    for (int j = 0; j < S / NWARP_ATTN; j += 4) {
        ATTN_STEP2(ev0, ev1, j);
        ATTN_STEP2(ev2, ev3, j + 2);
    }
#undef ATTN_STEP2

    __shared__ float sm_m[NWARP_ATTN];
    __shared__ float sm_l[NWARP_ATTN];
    __shared__ float sm_ctx[NWARP_ATTN][H];
#pragma unroll
    for (int i = 0; i < 4; i++)
        ((float4*)sm_ctx[warp])[lane + 32 * i] = ctx[i];
    if (lane == 0) { sm_m[warp] = m; sm_l[warp] = l; }
    __syncthreads();

    float mg = -1e30f;
#pragma unroll
    for (int w = 0; w < NWARP_ATTN; w++) mg = fmaxf(mg, sm_m[w]);
    float lg = 0.f, c = 0.f;
#pragma unroll
    for (int w = 0; w < NWARP_ATTN; w++) {
        float sc = __expf(sm_m[w] - mg);
        lg += sc * sm_l[w];
        c += sc * sm_ctx[w][t];
    }
    float inv = 1.f / lg;
    g_hcat[b * 1024 + 512 + t] = c * inv;

    for (int s = t; s < S; s += 512)
        attn_out[b * S + s] = __expf(attn_out[b * S + s] - mg) * inv;
}

// ---------------- launch ----------------
extern "C" void kernel_launch(void* const* d_in, const int* in_sizes, int n_in,
                              void* d_out, int out_size) {
    const int*   idx  = (const int*)  d_in[0];
    const float* h0   = (const float*)d_in[1];
    const float* enc  = (const float*)d_in[2];
    const float* emb  = (const float*)d_in[3];
    const float* wih  = (const float*)d_in[4];
    const float* whh  = (const float*)d_in[5];
    const float* bih  = (const float*)d_in[6];
    const float* bhh  = (const float*)d_in[7];
    const float* Wc   = (const float*)d_in[8];
    const float* bc   = (const float*)d_in[9];
    const float* Wout = (const float*)d_in[10];
    const float* bout = (const float*)d_in[11];

    float* out_logits = (float*)d_out;                 // B*V
    float* out_h      = out_logits + (size_t)B * V;    // B*H
    float* out_attn   = out_h + (size_t)B * H;         // B*S

    float* gp_p; cudaGetSymbolAddress((void**)&gp_p, g_gpart);
    float* cp_p; cudaGetSymbolAddress((void**)&cp_p, g_cpart);
    float* hc_p; cudaGetSymbolAddress((void**)&hc_p, g_hcat);
    __nv_bfloat16* ch_p; cudaGetSymbolAddress((void**)&ch_p, g_ch);
    __nv_bfloat16* cl_p; cudaGetSymbolAddress((void**)&cl_p, g_cl);

    cudaFuncSetAttribute(k_gemm<false>, cudaFuncAttributeMaxDynamicSharedMemorySize, GEMM_SMEM);
    cudaFuncSetAttribute(k_gemm<true>, cudaFuncAttributeMaxDynamicSharedMemorySize, GEMM_SMEM);

    // 1) GRU gate GEMMs (split-K x8): partials into g_gpart
    k_gemm<false><<<dim3(G / 128, 2, CH_G), NTHR, GEMM_SMEM>>>(
        emb, h0, idx, (const int*)nullptr,
        (const __nv_bfloat16*)nullptr, (const __nv_bfloat16*)nullptr,
        wih, whh, (const float*)nullptr, (const float*)nullptr,
        gp_p, gp_p + (size_t)CH_G * B * G,
        H, G, (H / KT) / CH_G, 1);
    // 2) fused GRU + attention
    k_attn<<<B, 512>>>(enc, out_attn, h0, bih, bhh, out_h);
    // 3) concat GEMM (split-K x16): partials into g_cpart
    k_gemm<false><<<dim3(H / 128, 1, CH_C), NTHR, GEMM_SMEM>>>(
        hc_p, hc_p, (const int*)nullptr, (const int*)nullptr,
        (const __nv_bfloat16*)nullptr, (const __nv_bfloat16*)nullptr,
        Wc, Wc, (const float*)nullptr, (const float*)nullptr,
        cp_p, cp_p,
        1024, H, (1024 / KT) / CH_C, 1);
    // 4) concat reduction + tanh + bf16 hi/lo split
    k_cfin<<<(B * H) / 256, 256>>>(bc);
    // 5) output GEMM (A pre-split bf16, through smem/ldmatrix)
    k_gemm<true><<<dim3(V / 128, 1, 1), NTHR, GEMM_SMEM>>>(
        (const float*)nullptr, (const float*)nullptr, (const int*)nullptr, (const int*)nullptr,
        ch_p, cl_p,
        Wout, Wout, bout, bout,
        out_logits, out_logits,
        H, V, H / KT, 0);
}